// round 1
// baseline (speedup 1.0000x reference)
#include <cuda_runtime.h>

// Problem constants: logits [B, 6, 512, 512] fp32, class_gt [B, 5] fp32, B=32.
#define NCLS   5
#define HW     (512 * 512)
#define G      (HW / 4)          // float4 groups per channel = 65536
#define CHUNKS 32                // blocks per image
#define TPB    256
#define GPC    (G / CHUNKS)      // 2048 float4 groups per block
#define ITERS  (GPC / TPB)       // 8 iterations per thread
#define MAXB   64

// Fixed-slot partials: every block writes its own slot -> deterministic, no
// atomics, no zero-init required.
__device__ float g_part_s[MAXB * CHUNKS * NCLS];
__device__ int   g_part_c[MAXB * CHUNKS * NCLS];

__global__ void __launch_bounds__(TPB)
apcl_accum_kernel(const float4* __restrict__ logits)
{
    const int b     = blockIdx.y;
    const int chunk = blockIdx.x;
    const int t     = threadIdx.x;

    // Image base: 6 channels of G float4 each; we touch only channels 0..4.
    const float4* base = logits + (size_t)b * 6 * G;

    float s[NCLS];
    int   cnt[NCLS];
#pragma unroll
    for (int c = 0; c < NCLS; c++) { s[c] = 0.0f; cnt[c] = 0; }

    const int g0 = chunk * GPC + t;

#pragma unroll
    for (int it = 0; it < ITERS; it++) {
        const int g = g0 + it * TPB;

        float4 v[NCLS];
#pragma unroll
        for (int c = 0; c < NCLS; c++)
            v[c] = __ldg(base + (size_t)c * G + g);

#pragma unroll
        for (int l = 0; l < 4; l++) {
            float x[NCLS];
#pragma unroll
            for (int c = 0; c < NCLS; c++)
                x[c] = ((const float*)&v[c])[l];

            const float m = fmaxf(fmaxf(fmaxf(x[0], x[1]), fmaxf(x[2], x[3])), x[4]);

            float e[NCLS];
            float sum = 0.0f;
#pragma unroll
            for (int c = 0; c < NCLS; c++) {
                e[c] = __expf(x[c] - m);
                sum += e[c];
            }

            // argmax over softmax numerators, ties -> lowest index (matches
            // jnp.argmax on pred; exp is monotone and e[true argmax] == 1).
            int   idx = 0;
            float be  = e[0];
#pragma unroll
            for (int c = 1; c < NCLS; c++) {
                if (e[c] > be) { be = e[c]; idx = c; }
            }

            // pred at argmax = e[idx]/sum with e[idx] == 1 exactly.
            const float p = 1.0f / sum;

#pragma unroll
            for (int c = 0; c < NCLS; c++) {
                if (idx == c) { s[c] += p; cnt[c]++; }
            }
        }
    }

    // --- warp reduction (fixed order, deterministic) ---
#pragma unroll
    for (int off = 16; off > 0; off >>= 1) {
#pragma unroll
        for (int c = 0; c < NCLS; c++) {
            s[c]   += __shfl_down_sync(0xffffffffu, s[c],   off);
            cnt[c] += __shfl_down_sync(0xffffffffu, cnt[c], off);
        }
    }

    __shared__ float sw[TPB / 32][NCLS];
    __shared__ int   cw[TPB / 32][NCLS];
    const int lane = t & 31;
    const int warp = t >> 5;
    if (lane == 0) {
#pragma unroll
        for (int c = 0; c < NCLS; c++) { sw[warp][c] = s[c]; cw[warp][c] = cnt[c]; }
    }
    __syncthreads();

    if (t < NCLS) {
        float acc = 0.0f;
        int   ca  = 0;
#pragma unroll
        for (int w = 0; w < TPB / 32; w++) { acc += sw[w][t]; ca += cw[w][t]; }
        const int slot = (b * CHUNKS + chunk) * NCLS + t;
        g_part_s[slot] = acc;
        g_part_c[slot] = ca;
    }
}

__global__ void __launch_bounds__(256)
apcl_finalize_kernel(const float* __restrict__ class_gt, float* __restrict__ out, int B)
{
    const int t = threadIdx.x;
    float term = 0.0f;

    if (t < B * NCLS) {
        const int b = t / NCLS;
        const int c = t % NCLS;
        float S = 0.0f;
        int   N = 0;
#pragma unroll
        for (int k = 0; k < CHUNKS; k++) {
            const int slot = (b * CHUNKS + k) * NCLS + c;
            S += g_part_s[slot];
            N += g_part_c[slot];
        }
        // cnt > 0 -> S / cnt ; cnt == 0 -> agg = 0 (log terms then hit clamps)
        const float agg = (N > 0) ? (S / (float)N) : 0.0f;
        const float g   = class_gt[t];
        const float lp  = fmaxf(logf(agg),     -100.0f);  // log(0) = -inf -> -100
        const float l1  = fmaxf(log1pf(-agg),  -100.0f);  // log1p(-1) = -inf -> -100
        term = g * lp + (1.0f - g) * l1;
    }

    __shared__ float red[256];
    red[t] = term;
    __syncthreads();
#pragma unroll
    for (int o = 128; o > 0; o >>= 1) {
        if (t < o) red[t] += red[t + o];
        __syncthreads();
    }
    if (t == 0)
        out[0] = -red[0] / (float)(B * NCLS);
}

extern "C" void kernel_launch(void* const* d_in, const int* in_sizes, int n_in,
                              void* d_out, int out_size)
{
    // metadata order: segmentation_logits (large), class_gt (small).
    // Be defensive about ordering by picking the larger buffer as logits.
    int li = 0, gi = 1;
    if (n_in >= 2 && in_sizes[1] > in_sizes[0]) { li = 1; gi = 0; }

    const float* logits = (const float*)d_in[li];
    const float* gt     = (const float*)d_in[gi];

    int B = in_sizes[gi] / NCLS;   // 32
    if (B < 1)    B = 1;
    if (B > MAXB) B = MAXB;

    dim3 grid(CHUNKS, B);
    apcl_accum_kernel<<<grid, TPB>>>((const float4*)logits);
    apcl_finalize_kernel<<<1, 256>>>(gt, (float*)d_out, B);
}

// round 2
// speedup vs baseline: 1.0730x; 1.0730x over previous
#include <cuda_runtime.h>

// Problem constants: logits [B, 6, 512, 512] fp32, class_gt [B, 5] fp32, B=32.
#define NCLS   5
#define HW     (512 * 512)
#define G      (HW / 4)          // float4 groups per channel = 65536
#define CHUNKS 64                // blocks per image
#define TPB    256
#define GPC    (G / CHUNKS)      // 1024 float4 groups per block
#define ITERS  (GPC / TPB)       // 4 iterations per thread
#define MAXB   64

// Fixed-slot partials: every block writes its own slot -> deterministic, no
// FP atomics, no zero-init required (every slot written every call).
__device__ float        g_part_s[MAXB * CHUNKS * NCLS];
__device__ int          g_part_c[MAXB * CHUNKS * NCLS];
__device__ unsigned int g_ticket;   // zero-initialized; reset by last block each call

__global__ void __launch_bounds__(TPB)
apcl_fused_kernel(const float4* __restrict__ logits,
                  const float*  __restrict__ class_gt,
                  float*        __restrict__ out,
                  int B)
{
    const int b      = blockIdx.y;
    const int chunk  = blockIdx.x;
    const int t      = threadIdx.x;
    const int nblk   = gridDim.x * gridDim.y;

    // Image base: 6 channels of G float4 each; we touch only channels 0..4.
    const float4* base = logits + (size_t)b * 6 * G;

    float s[NCLS];
    int   cnt[NCLS];
#pragma unroll
    for (int c = 0; c < NCLS; c++) { s[c] = 0.0f; cnt[c] = 0; }

    const int g0 = chunk * GPC + t;

#pragma unroll
    for (int it = 0; it < ITERS; it++) {
        const int g = g0 + it * TPB;

        float4 v[NCLS];
#pragma unroll
        for (int c = 0; c < NCLS; c++)
            v[c] = __ldcg(base + (size_t)c * G + g);   // streaming: bypass L1

#pragma unroll
        for (int l = 0; l < 4; l++) {
            float x[NCLS];
#pragma unroll
            for (int c = 0; c < NCLS; c++)
                x[c] = ((const float*)&v[c])[l];

            const float m = fmaxf(fmaxf(fmaxf(x[0], x[1]), fmaxf(x[2], x[3])), x[4]);

            float sum = 0.0f;
#pragma unroll
            for (int c = 0; c < NCLS; c++)
                sum += __expf(x[c] - m);

            // argmax over x (exp is monotone => same index as argmax over pred;
            // ties -> lowest index, matching jnp.argmax / torch.max).
            int   idx = 0;
            float bx  = x[0];
#pragma unroll
            for (int c = 1; c < NCLS; c++) {
                if (x[c] > bx) { bx = x[c]; idx = c; }
            }

            // pred at argmax = exp(0)/sum = 1/sum exactly.
            const float p = __fdividef(1.0f, sum);

#pragma unroll
            for (int c = 0; c < NCLS; c++) {
                if (idx == c) { s[c] += p; cnt[c]++; }
            }
        }
    }

    // --- warp reduction (fixed order, deterministic) ---
#pragma unroll
    for (int off = 16; off > 0; off >>= 1) {
#pragma unroll
        for (int c = 0; c < NCLS; c++) {
            s[c]   += __shfl_down_sync(0xffffffffu, s[c],   off);
            cnt[c] += __shfl_down_sync(0xffffffffu, cnt[c], off);
        }
    }

    __shared__ float sw[TPB / 32][NCLS];
    __shared__ int   cw[TPB / 32][NCLS];
    const int lane = t & 31;
    const int warp = t >> 5;
    if (lane == 0) {
#pragma unroll
        for (int c = 0; c < NCLS; c++) { sw[warp][c] = s[c]; cw[warp][c] = cnt[c]; }
    }
    __syncthreads();

    if (t < NCLS) {
        float acc = 0.0f;
        int   ca  = 0;
#pragma unroll
        for (int w = 0; w < TPB / 32; w++) { acc += sw[w][t]; ca += cw[w][t]; }
        const int slot = (b * CHUNKS + chunk) * NCLS + t;
        g_part_s[slot] = acc;
        g_part_c[slot] = ca;
    }

    // --- last-block-done finalize (single launch, no second kernel) ---
    __shared__ int is_last;
    __threadfence();                       // partials visible before ticket
    if (t == 0) {
        unsigned int old = atomicAdd(&g_ticket, 1u);
        is_last = (old == (unsigned int)(nblk - 1)) ? 1 : 0;
    }
    __syncthreads();
    if (!is_last) return;

    // This is the last block: all partials are globally visible.
    float term = 0.0f;
    const int NT = B * NCLS;               // 160
    if (t < NT) {
        const int bb = t / NCLS;
        const int cc = t % NCLS;
        float S = 0.0f;
        int   N = 0;
#pragma unroll
        for (int k = 0; k < CHUNKS; k++) {
            const int slot = (bb * CHUNKS + k) * NCLS + cc;
            S += __ldcg(&g_part_s[slot]);  // bypass L1: written by other SMs
            N += __ldcg(&g_part_c[slot]);
        }
        const float agg = (N > 0) ? (S / (float)N) : 0.0f;
        const float gt  = class_gt[t];
        const float lp  = fmaxf(logf(agg),    -100.0f);  // log(0)=-inf -> -100
        const float l1  = fmaxf(log1pf(-agg), -100.0f);  // log1p(-1)=-inf -> -100
        term = gt * lp + (1.0f - gt) * l1;
    }

    __shared__ float red[TPB];
    red[t] = term;
    __syncthreads();
#pragma unroll
    for (int o = TPB / 2; o > 0; o >>= 1) {
        if (t < o) red[t] += red[t + o];
        __syncthreads();
    }
    if (t == 0) {
        out[0] = -red[0] / (float)NT;
        g_ticket = 0;                      // reset for next graph replay
    }
}

extern "C" void kernel_launch(void* const* d_in, const int* in_sizes, int n_in,
                              void* d_out, int out_size)
{
    // metadata order: segmentation_logits (large), class_gt (small).
    int li = 0, gi = 1;
    if (n_in >= 2 && in_sizes[1] > in_sizes[0]) { li = 1; gi = 0; }

    const float* logits = (const float*)d_in[li];
    const float* gt     = (const float*)d_in[gi];

    int B = in_sizes[gi] / NCLS;   // 32
    if (B < 1)    B = 1;
    if (B > MAXB) B = MAXB;

    dim3 grid(CHUNKS, B);
    apcl_fused_kernel<<<grid, TPB>>>((const float4*)logits, gt, (float*)d_out, B);
}